// round 15
// baseline (speedup 1.0000x reference)
#include <cuda_runtime.h>
#include <cuda_fp16.h>
#include <cstdint>

// ---------------------------------------------------------------------------
// Problem constants
// ---------------------------------------------------------------------------
#define NB   4
#define NTOK 2048
#define NC   1024
#define MTOT (NB * NTOK)   // 8192
#define NSM_CTAS 296       // 2 CTAs x 148 SMs

// Scratch (__device__ globals: allocation-free rule)
__device__ __half g_x [(size_t)MTOT * NC];          // fp16 x
__device__ __half g_w [(size_t)3 * NC * NC];        // fp16 Wk|Wq|Wv
__device__ float  g_b [3 * NC];                     // concat bk|bq|bv (fp32)
__device__ __half g_q [(size_t)MTOT * NC];
__device__ __half g_k [(size_t)MTOT * NC];
__device__ __half g_vt[(size_t)NC * MTOT];          // V transposed: [C][B*T]
__device__ __half g_p [(size_t)NB * NTOK * NTOK];   // P' = exp(S) (fp16, masked)
__device__ float  g_part[(size_t)MTOT * 32];        // per-(tile,warp-half) row partials
__device__ float  g_inv[MTOT];                      // 1 / row sums of P'

__device__ __forceinline__ void mma_f16(float c[4], const uint32_t a[4],
                                        uint32_t b0, uint32_t b1) {
    asm volatile(
        "mma.sync.aligned.m16n8k16.row.col.f32.f16.f16.f32 "
        "{%0,%1,%2,%3}, {%4,%5,%6,%7}, {%8,%9}, {%0,%1,%2,%3};"
        : "+f"(c[0]), "+f"(c[1]), "+f"(c[2]), "+f"(c[3])
        : "r"(a[0]), "r"(a[1]), "r"(a[2]), "r"(a[3]), "r"(b0), "r"(b1));
}

__device__ __forceinline__ void ldsm_x4(uint32_t& r0, uint32_t& r1,
                                        uint32_t& r2, uint32_t& r3,
                                        uint32_t addr) {
    asm volatile("ldmatrix.sync.aligned.m8n8.x4.shared.b16 {%0,%1,%2,%3}, [%4];"
                 : "=r"(r0), "=r"(r1), "=r"(r2), "=r"(r3) : "r"(addr));
}

__device__ __forceinline__ uint32_t smem_u32(const void* p) {
    uint32_t a;
    asm("{ .reg .u64 t; cvta.to.shared.u64 t, %1; cvt.u32.u64 %0, t; }"
        : "=r"(a) : "l"(p));
    return a;
}

__device__ __forceinline__ void cp16(uint32_t dst, const void* src) {
    asm volatile("cp.async.cg.shared.global [%0], [%1], 16;"
                 :: "r"(dst), "l"(src));
}
#define CP_COMMIT()   asm volatile("cp.async.commit_group;" ::: "memory")
#define CP_WAIT1()    asm volatile("cp.async.wait_group 1;" ::: "memory")
#define CP_WAITALL()  asm volatile("cp.async.wait_all;" ::: "memory")

// ---------------------------------------------------------------------------
// Persistent fp16 mma.sync NT GEMM, cp.async 3-stage pipeline, BK=64 halfs.
// Block tile 128x128, 128 threads (4 warps, 2m x 2n), warp tile 64x64.
// 2 CTAs/SM; NSM_CTAS persistent CTAs loop over tiles.
// mode 0: QKV  — route cols to P0|P1|P2^T (fp16), +bias.
// mode 1: scores — lower-tri tiles; epilogue writes exp(alpha*S) fp16 to P0
//                  (causal mask col<=row) and per-row PARTIAL sums to part[]
//                  (one unique fp32 slot per (row, n-tile, warp-half); no atomics).
// mode 2: PV  — K truncated at bm+128, load-balanced rank mapping; epilogue
//               scales rows by rowinv[] (softmax normalization), C fp32.
// ---------------------------------------------------------------------------
#define STAGES 3
#define BMT 128
#define BNT 128
#define BK  64
#define ASTR_H 72                        // halfs per smem row (144 B)
#define ABUF_H (BMT * ASTR_H)            // 9216 halfs
#define STG_B  (2 * ABUF_H * 2)          // bytes per stage (A+B) = 36864
#define SMEM_BYTES (STAGES * STG_B)      // 110592

__device__ __forceinline__ void issue_loads(uint32_t sbase,
                                            const __half* Ab, const __half* Bb,
                                            long lda, long ldb, long koff, int tid)
{
    #pragma unroll
    for (int i = 0; i < 8; i++) {
        const int idx = i * 128 + tid;          // 0..1023
        const int row = idx >> 3;               // 0..127
        const int kq  = (idx & 7) * 8;          // halfs: 0..56
        cp16(sbase + (uint32_t)(row * ASTR_H + kq) * 2,
             Ab + (size_t)row * lda + koff + kq);
    }
    #pragma unroll
    for (int i = 0; i < 8; i++) {
        const int idx = i * 128 + tid;
        const int row = idx >> 3;
        const int kq  = (idx & 7) * 8;
        cp16(sbase + (uint32_t)(ABUF_H + row * ASTR_H + kq) * 2,
             Bb + (size_t)row * ldb + koff + kq);
    }
}

__global__ void __launch_bounds__(128, 2)
tc_gemm(const __half* __restrict__ A, const __half* __restrict__ B,
        const float* __restrict__ bias, float* __restrict__ C,
        __half* __restrict__ P0, __half* __restrict__ P1, __half* __restrict__ P2,
        float* __restrict__ aux,            // mode1: part[]; mode2: rowinv[]
        int K, long lda, long ldb, long ldc,
        long sA, long sB, long sC,
        float alpha, int mode, int ntiles)
{
    extern __shared__ __half sm[];

    const int tid  = threadIdx.x;
    const int wid  = tid >> 5;
    const int lane = tid & 31;
    const int wm   = (wid & 1) * 64;
    const int wn   = (wid >> 1) * 64;
    const int grp  = lane >> 2;
    const int kin  = lane & 3;

    const int mat = lane >> 3;          // 0..3
    const int r8  = lane & 7;
    const uint32_t smb = smem_u32(sm);
    const uint32_t aaddr0 = smb +
        (uint32_t)(wm + (mat & 1) * 8 + r8) * (ASTR_H * 2) + (mat >> 1) * 16;
    const uint32_t baddr0 = smb + ABUF_H * 2 +
        (uint32_t)(wn + (mat & 1) * 8 + r8) * (ASTR_H * 2) + (mat >> 1) * 16;

    for (int t = blockIdx.x; t < ntiles; t += gridDim.x) {
        // ---- tile mapping ----
        int bm, bn, z, nch;
        if (mode == 0) {                     // QKV: 24 n-tiles x 64 m-tiles
            bm = (t / 24) * BMT;
            bn = (t % 24) * BNT;
            z  = 0;
            nch = K / BK;
        } else if (mode == 1) {              // scores: lower-tri tiles, 136/batch
            z = t / 136;
            const int tri = t - z * 136;
            int i = (int)((sqrtf(8.0f * tri + 1.0f) - 1.0f) * 0.5f);
            while ((i + 1) * (i + 2) / 2 <= tri) i++;
            while (i * (i + 1) / 2 > tri) i--;
            const int j = tri - i * (i + 1) / 2;
            bm = i * BMT;
            bn = j * BNT;
            nch = K / BK;
        } else {
            // PV: load-balanced rank mapping for persistent stride of 296.
            int rank;
            if (t >= 216 && t < 296)      rank = t - 216;       // 0..79
            else if (t < 216)             rank = 80 + t;        // 80..295
            else                          rank = 807 - t;       // 296..511
            const int level = rank >> 5;       // 0..15 (heavy -> light)
            const int idx   = rank & 31;
            bm = (15 - level) * BMT;
            z  = idx >> 3;
            bn = (idx & 7) * BNT;
            nch = (bm + BMT) / BK;
        }

        const __half* Ab = A + (size_t)z * sA + (size_t)bm * lda;
        const __half* Bb = B + (size_t)z * sB + (size_t)bn * ldb;
        float*        Cb = C ? (C + (size_t)z * sC) : nullptr;

        float acc[4][8][4] = {};

        // ---- prologue: prefetch STAGES-1 chunks ----
        #pragma unroll
        for (int s = 0; s < STAGES - 1; s++) {
            if (s < nch)
                issue_loads(smb + (uint32_t)s * STG_B, Ab, Bb, lda, ldb,
                            (long)s * BK, tid);
            CP_COMMIT();
        }

        for (int kc = 0; kc < nch; kc++) {
            CP_WAIT1();
            __syncthreads();

            const int nk = kc + STAGES - 1;
            if (nk < nch)
                issue_loads(smb + (uint32_t)(nk % STAGES) * STG_B,
                            Ab, Bb, lda, ldb, (long)nk * BK, tid);
            CP_COMMIT();

            const uint32_t soff = (uint32_t)(kc % STAGES) * STG_B;
            const uint32_t abase = aaddr0 + soff;
            const uint32_t bbase = baddr0 + soff;

            #pragma unroll
            for (int ks = 0; ks < 4; ks++) {       // 4 x k16 = 64
                uint32_t a[4][4];
                #pragma unroll
                for (int mt = 0; mt < 4; mt++)
                    ldsm_x4(a[mt][0], a[mt][1], a[mt][2], a[mt][3],
                            abase + mt * (16 * ASTR_H * 2) + ks * 32);
                #pragma unroll
                for (int np = 0; np < 4; np++) {   // n16 groups
                    uint32_t b0, b1, b2, b3;
                    ldsm_x4(b0, b1, b2, b3,
                            bbase + np * (16 * ASTR_H * 2) + ks * 32);
                    #pragma unroll
                    for (int mt = 0; mt < 4; mt++) {
                        mma_f16(acc[mt][np * 2    ], a[mt], b0, b2);
                        mma_f16(acc[mt][np * 2 + 1], a[mt], b1, b3);
                    }
                }
            }
        }
        CP_WAITALL();
        __syncthreads();   // all smem reads done before next tile's prologue

        // ---- epilogue ----
        #pragma unroll
        for (int mt = 0; mt < 4; mt++) {
            const int row = bm + wm + mt * 16 + grp;
            float s0 = 1.f, s1 = 1.f;
            if (mode == 2) {
                s0 = aux[z * NTOK + row];
                s1 = aux[z * NTOK + row + 8];
            }
            float rs_lo = 0.f, rs_hi = 0.f;
            #pragma unroll
            for (int nt = 0; nt < 8; nt++) {
                const int col = bn + wn + nt * 8 + kin * 2;
                float c0 = acc[mt][nt][0] * alpha;
                float c1 = acc[mt][nt][1] * alpha;
                float c2 = acc[mt][nt][2] * alpha;
                float c3 = acc[mt][nt][3] * alpha;
                if (mode == 0) {
                    const float bz0 = bias[col], bz1 = bias[col + 1];
                    c0 += bz0; c1 += bz1; c2 += bz0; c3 += bz1;
                    const int seg = col >> 10;          // uniform per tile
                    const int cc  = col & 1023;
                    if (seg == 0) {
                        *(__half2*)(P0 + (size_t)row * NC + cc)       = __floats2half2_rn(c0, c1);
                        *(__half2*)(P0 + (size_t)(row + 8) * NC + cc) = __floats2half2_rn(c2, c3);
                    } else if (seg == 1) {
                        *(__half2*)(P1 + (size_t)row * NC + cc)       = __floats2half2_rn(c0, c1);
                        *(__half2*)(P1 + (size_t)(row + 8) * NC + cc) = __floats2half2_rn(c2, c3);
                    } else {
                        P2[(size_t)(cc    ) * MTOT + row    ] = __float2half_rn(c0);
                        P2[(size_t)(cc + 1) * MTOT + row    ] = __float2half_rn(c1);
                        P2[(size_t)(cc    ) * MTOT + row + 8] = __float2half_rn(c2);
                        P2[(size_t)(cc + 1) * MTOT + row + 8] = __float2half_rn(c3);
                    }
                } else if (mode == 1) {
                    // exp + causal mask, unnormalized P' in fp16; partial sums
                    __half* Pb = P0 + (size_t)z * sC;
                    float e0 = (col     <= row) ? __expf(c0) : 0.f;
                    float e1 = (col + 1 <= row) ? __expf(c1) : 0.f;
                    float e2 = (col     <= row + 8) ? __expf(c2) : 0.f;
                    float e3 = (col + 1 <= row + 8) ? __expf(c3) : 0.f;
                    rs_lo += e0 + e1;
                    rs_hi += e2 + e3;
                    *(__half2*)(Pb + (size_t)row * ldc + col)       = __floats2half2_rn(e0, e1);
                    *(__half2*)(Pb + (size_t)(row + 8) * ldc + col) = __floats2half2_rn(e2, e3);
                } else {
                    *(float2*)(Cb + (size_t)row * ldc + col) =
                        make_float2(c0 * s0, c1 * s0);
                    *(float2*)(Cb + (size_t)(row + 8) * ldc + col) =
                        make_float2(c2 * s1, c3 * s1);
                }
            }
            if (mode == 1) {
                // reduce over the 4 kin lanes sharing this row, then one
                // unique partial slot per (row, n-tile, warp-half): no atomics
                #pragma unroll
                for (int o = 1; o < 4; o <<= 1) {
                    rs_lo += __shfl_xor_sync(0xffffffffu, rs_lo, o);
                    rs_hi += __shfl_xor_sync(0xffffffffu, rs_hi, o);
                }
                if (kin == 0) {
                    const int slot = (bn >> 7) * 2 + (wn >> 6);   // 0..31
                    g_part[(size_t)(z * NTOK + row)     * 32 + slot] = rs_lo;
                    g_part[(size_t)(z * NTOK + row + 8) * 32 + slot] = rs_hi;
                }
            }
        }
    }
}

// ---------------------------------------------------------------------------
// Merged prep: fp16-convert x + Wk|Wq|Wv, concat biases (single launch)
// ---------------------------------------------------------------------------
__global__ void prep_all(const float4* __restrict__ x,
                         const float4* __restrict__ wk,
                         const float4* __restrict__ wq,
                         const float4* __restrict__ wv,
                         const float*  __restrict__ bk,
                         const float*  __restrict__ bq,
                         const float*  __restrict__ bv,
                         __half2* __restrict__ xr, __half2* __restrict__ wr,
                         float* __restrict__ bb,
                         int n4x, int n4w)
{
    const int i = blockIdx.x * blockDim.x + threadIdx.x;
    const int n4t = n4x + 3 * n4w;
    if (i < n4t) {
        const float4* src;
        __half2* dst;
        int j;
        if (i < n4x)                { src = x;  dst = xr;                       j = i; }
        else if (i < n4x + n4w)     { src = wk; dst = wr;                       j = i - n4x; }
        else if (i < n4x + 2 * n4w) { src = wq; dst = wr + (size_t)n4w * 2;     j = i - n4x - n4w; }
        else                        { src = wv; dst = wr + (size_t)n4w * 4;     j = i - n4x - 2 * n4w; }
        const float4 v = src[j];
        dst[j * 2    ] = __floats2half2_rn(v.x, v.y);
        dst[j * 2 + 1] = __floats2half2_rn(v.z, v.w);
    } else {
        const int b = i - n4t;
        if (b < NC) {
            bb[b]          = bk[b];
            bb[NC + b]     = bq[b];
            bb[2 * NC + b] = bv[b];
        }
    }
}

// ---------------------------------------------------------------------------
// Finish row sums: inv[row] = 1 / sum of written partials (<=32 per row).
// Only slots for n-tiles j <= (t>>7) were written; read exactly those.
// ---------------------------------------------------------------------------
__global__ void finish_sums(float* __restrict__ inv)
{
    const int row = blockIdx.x * blockDim.x + threadIdx.x;
    if (row >= MTOT) return;
    const int t = row & (NTOK - 1);
    const int njt = (t >> 7) + 1;               // written n-tiles
    const float* pr = g_part + (size_t)row * 32;
    float s = 0.f;
    for (int j = 0; j < njt; j++)
        s += pr[j * 2] + pr[j * 2 + 1];
    inv[row] = 1.0f / s;
}

// ---------------------------------------------------------------------------
// Launch
// ---------------------------------------------------------------------------
extern "C" void kernel_launch(void* const* d_in, const int* in_sizes, int n_in,
                              void* d_out, int out_size)
{
    const float* x  = (const float*)d_in[0];
    const float* Wk = (const float*)d_in[1];
    const float* bk = (const float*)d_in[2];
    const float* Wq = (const float*)d_in[3];
    const float* bq = (const float*)d_in[4];
    const float* Wv = (const float*)d_in[5];
    const float* bv = (const float*)d_in[6];
    float* y = (float*)d_out;

    __half *xr, *wr, *q, *k, *vt, *pp;
    float *bb, *ginv;
    cudaGetSymbolAddress((void**)&xr, g_x);
    cudaGetSymbolAddress((void**)&wr, g_w);
    cudaGetSymbolAddress((void**)&bb, g_b);
    cudaGetSymbolAddress((void**)&q,  g_q);
    cudaGetSymbolAddress((void**)&k,  g_k);
    cudaGetSymbolAddress((void**)&vt, g_vt);
    cudaGetSymbolAddress((void**)&pp, g_p);
    cudaGetSymbolAddress((void**)&ginv, g_inv);

    cudaFuncSetAttribute(tc_gemm, cudaFuncAttributeMaxDynamicSharedMemorySize,
                         SMEM_BYTES);

    // 0) single prep launch: fp16 conversions + bias concat
    const int n4x = MTOT * NC / 4;
    const int n4w = NC * NC / 4;
    const int ntot = n4x + 3 * n4w + NC;
    prep_all<<<(ntot + 255) / 256, 256>>>((const float4*)x, (const float4*)Wk,
                                          (const float4*)Wq, (const float4*)Wv,
                                          bk, bq, bv,
                                          (__half2*)xr, (__half2*)wr, bb,
                                          n4x, n4w);

    // 1) Fused QKV projection (persistent): 1536 tiles
    tc_gemm<<<NSM_CTAS, 128, SMEM_BYTES>>>(xr, wr, bb, nullptr, k, q, vt, nullptr,
                                           NC, NC, NC, 0, 0, 0, 0,
                                           1.0f, 0, 1536);

    // 2) Scores (persistent): 544 lower-tri tiles -> P' = exp(alpha*S) fp16,
    //    per-row partial sums written (no atomics)
    tc_gemm<<<NSM_CTAS, 128, SMEM_BYTES>>>(q, k, nullptr, nullptr, pp, nullptr,
                                           nullptr, nullptr,
                                           NC, NC, NC, NTOK,
                                           (long)NTOK * NC, (long)NTOK * NC,
                                           (long)NTOK * NTOK,
                                           0.03125f, 1, 544);

    // 3) Finish row sums -> inv (reads <=32 partials per row)
    finish_sums<<<MTOT / 256, 256>>>(ginv);

    // 4) Y = diag(inv) * (P' @ V) (persistent): 512 tiles, balanced ranks
    tc_gemm<<<NSM_CTAS, 128, SMEM_BYTES>>>(pp, vt, nullptr, y, nullptr, nullptr,
                                           nullptr, ginv,
                                           NTOK, NTOK, MTOT, NC,
                                           (long)NTOK * NTOK, (long)NTOK,
                                           (long)NTOK * NC,
                                           1.0f, 2, 512);
}

// round 16
// speedup vs baseline: 1.0246x; 1.0246x over previous
#include <cuda_runtime.h>
#include <cuda_fp16.h>
#include <cstdint>

// ---------------------------------------------------------------------------
// Problem constants
// ---------------------------------------------------------------------------
#define NB   4
#define NTOK 2048
#define NC   1024
#define MTOT (NB * NTOK)   // 8192
#define NSM_CTAS 296       // 2 CTAs x 148 SMs

// Scratch (__device__ globals: allocation-free rule)
__device__ __half g_x [(size_t)MTOT * NC];          // fp16 x
__device__ __half g_w [(size_t)3 * NC * NC];        // fp16 Wk|Wq|Wv
__device__ float  g_b [3 * NC];                     // concat bk|bq|bv (fp32)
__device__ __half g_q [(size_t)MTOT * NC];
__device__ __half g_k [(size_t)MTOT * NC];
__device__ __half g_vt[(size_t)NC * MTOT];          // V transposed: [C][B*T]
__device__ __half g_p [(size_t)NB * NTOK * NTOK];   // P' = exp(S) (fp16, masked)
__device__ float  g_inv[MTOT];                      // 1 / row sums of P'

__device__ __forceinline__ void mma_f16(float c[4], const uint32_t a[4],
                                        uint32_t b0, uint32_t b1) {
    asm volatile(
        "mma.sync.aligned.m16n8k16.row.col.f32.f16.f16.f32 "
        "{%0,%1,%2,%3}, {%4,%5,%6,%7}, {%8,%9}, {%0,%1,%2,%3};"
        : "+f"(c[0]), "+f"(c[1]), "+f"(c[2]), "+f"(c[3])
        : "r"(a[0]), "r"(a[1]), "r"(a[2]), "r"(a[3]), "r"(b0), "r"(b1));
}

__device__ __forceinline__ void ldsm_x4(uint32_t& r0, uint32_t& r1,
                                        uint32_t& r2, uint32_t& r3,
                                        uint32_t addr) {
    asm volatile("ldmatrix.sync.aligned.m8n8.x4.shared.b16 {%0,%1,%2,%3}, [%4];"
                 : "=r"(r0), "=r"(r1), "=r"(r2), "=r"(r3) : "r"(addr));
}

__device__ __forceinline__ uint32_t smem_u32(const void* p) {
    uint32_t a;
    asm("{ .reg .u64 t; cvta.to.shared.u64 t, %1; cvt.u32.u64 %0, t; }"
        : "=r"(a) : "l"(p));
    return a;
}

__device__ __forceinline__ void cp16(uint32_t dst, const void* src) {
    asm volatile("cp.async.cg.shared.global [%0], [%1], 16;"
                 :: "r"(dst), "l"(src));
}
#define CP_COMMIT()   asm volatile("cp.async.commit_group;" ::: "memory")
#define CP_WAIT1()    asm volatile("cp.async.wait_group 1;" ::: "memory")
#define CP_WAITALL()  asm volatile("cp.async.wait_all;" ::: "memory")

// ---------------------------------------------------------------------------
// Persistent fp16 mma.sync NT GEMM, cp.async 3-stage pipeline, BK=64 halfs.
// Block tile 128x128, 256 threads (8 warps, 4m x 2n), warp tile 32x64.
// 2 CTAs/SM => 16 warps/SM for latency hiding.
// mode 0: QKV  — route cols to P0|P1|P2^T (fp16), +bias.
// mode 1: scores — lower-tri tiles; epilogue writes exp(alpha*S) fp16 to P0
//                  with causal mask col<=row.
// mode 2: PV  — K truncated at bm+128, load-balanced rank mapping; epilogue
//               scales rows by rowinv[] (softmax normalization), C fp32.
// ---------------------------------------------------------------------------
#define STAGES 3
#define BMT 128
#define BNT 128
#define BK  64
#define ASTR_H 72                        // halfs per smem row (144 B)
#define ABUF_H (BMT * ASTR_H)            // 9216 halfs
#define STG_B  (2 * ABUF_H * 2)          // bytes per stage (A+B) = 36864
#define SMEM_BYTES (STAGES * STG_B)      // 110592

__device__ __forceinline__ void issue_loads(uint32_t sbase,
                                            const __half* Ab, const __half* Bb,
                                            long lda, long ldb, long koff, int tid)
{
    #pragma unroll
    for (int i = 0; i < 4; i++) {
        const int idx = i * 256 + tid;          // 0..1023
        const int row = idx >> 3;               // 0..127
        const int kq  = (idx & 7) * 8;          // halfs: 0..56
        cp16(sbase + (uint32_t)(row * ASTR_H + kq) * 2,
             Ab + (size_t)row * lda + koff + kq);
    }
    #pragma unroll
    for (int i = 0; i < 4; i++) {
        const int idx = i * 256 + tid;
        const int row = idx >> 3;
        const int kq  = (idx & 7) * 8;
        cp16(sbase + (uint32_t)(ABUF_H + row * ASTR_H + kq) * 2,
             Bb + (size_t)row * ldb + koff + kq);
    }
}

__global__ void __launch_bounds__(256, 2)
tc_gemm(const __half* __restrict__ A, const __half* __restrict__ B,
        const float* __restrict__ bias, float* __restrict__ C,
        __half* __restrict__ P0, __half* __restrict__ P1, __half* __restrict__ P2,
        const float* __restrict__ rowinv,
        int K, long lda, long ldb, long ldc,
        long sA, long sB, long sC,
        float alpha, int mode, int ntiles)
{
    extern __shared__ __half sm[];

    const int tid  = threadIdx.x;
    const int wid  = tid >> 5;
    const int lane = tid & 31;
    const int wm   = (wid & 3) * 32;    // 4 m-warps
    const int wn   = (wid >> 2) * 64;   // 2 n-warps
    const int grp  = lane >> 2;
    const int kin  = lane & 3;

    const int mat = lane >> 3;          // 0..3
    const int r8  = lane & 7;
    const uint32_t smb = smem_u32(sm);
    const uint32_t aaddr0 = smb +
        (uint32_t)(wm + (mat & 1) * 8 + r8) * (ASTR_H * 2) + (mat >> 1) * 16;
    const uint32_t baddr0 = smb + ABUF_H * 2 +
        (uint32_t)(wn + (mat & 1) * 8 + r8) * (ASTR_H * 2) + (mat >> 1) * 16;

    for (int t = blockIdx.x; t < ntiles; t += gridDim.x) {
        // ---- tile mapping ----
        int bm, bn, z, nch;
        if (mode == 0) {                     // QKV: 24 n-tiles x 64 m-tiles
            bm = (t / 24) * BMT;
            bn = (t % 24) * BNT;
            z  = 0;
            nch = K / BK;
        } else if (mode == 1) {              // scores: lower-tri tiles, 136/batch
            z = t / 136;
            const int tri = t - z * 136;
            int i = (int)((sqrtf(8.0f * tri + 1.0f) - 1.0f) * 0.5f);
            while ((i + 1) * (i + 2) / 2 <= tri) i++;
            while (i * (i + 1) / 2 > tri) i--;
            const int j = tri - i * (i + 1) / 2;
            bm = i * BMT;
            bn = j * BNT;
            nch = K / BK;
        } else {
            // PV: load-balanced rank mapping for persistent stride of 296.
            int rank;
            if (t >= 216 && t < 296)      rank = t - 216;       // 0..79
            else if (t < 216)             rank = 80 + t;        // 80..295
            else                          rank = 807 - t;       // 296..511
            const int level = rank >> 5;       // 0..15 (heavy -> light)
            const int idx   = rank & 31;
            bm = (15 - level) * BMT;
            z  = idx >> 3;
            bn = (idx & 7) * BNT;
            nch = (bm + BMT) / BK;
        }

        const __half* Ab = A + (size_t)z * sA + (size_t)bm * lda;
        const __half* Bb = B + (size_t)z * sB + (size_t)bn * ldb;
        float*        Cb = C ? (C + (size_t)z * sC) : nullptr;

        float acc[2][8][4] = {};

        // ---- prologue: prefetch STAGES-1 chunks ----
        #pragma unroll
        for (int s = 0; s < STAGES - 1; s++) {
            if (s < nch)
                issue_loads(smb + (uint32_t)s * STG_B, Ab, Bb, lda, ldb,
                            (long)s * BK, tid);
            CP_COMMIT();
        }

        for (int kc = 0; kc < nch; kc++) {
            CP_WAIT1();
            __syncthreads();

            const int nk = kc + STAGES - 1;
            if (nk < nch)
                issue_loads(smb + (uint32_t)(nk % STAGES) * STG_B,
                            Ab, Bb, lda, ldb, (long)nk * BK, tid);
            CP_COMMIT();

            const uint32_t soff = (uint32_t)(kc % STAGES) * STG_B;
            const uint32_t abase = aaddr0 + soff;
            const uint32_t bbase = baddr0 + soff;

            #pragma unroll
            for (int ks = 0; ks < 4; ks++) {       // 4 x k16 = 64
                uint32_t a[2][4];
                #pragma unroll
                for (int mt = 0; mt < 2; mt++)
                    ldsm_x4(a[mt][0], a[mt][1], a[mt][2], a[mt][3],
                            abase + mt * (16 * ASTR_H * 2) + ks * 32);
                #pragma unroll
                for (int np = 0; np < 4; np++) {   // n16 groups
                    uint32_t b0, b1, b2, b3;
                    ldsm_x4(b0, b1, b2, b3,
                            bbase + np * (16 * ASTR_H * 2) + ks * 32);
                    #pragma unroll
                    for (int mt = 0; mt < 2; mt++) {
                        mma_f16(acc[mt][np * 2    ], a[mt], b0, b2);
                        mma_f16(acc[mt][np * 2 + 1], a[mt], b1, b3);
                    }
                }
            }
        }
        CP_WAITALL();
        __syncthreads();   // all smem reads done before next tile's prologue

        // ---- epilogue ----
        #pragma unroll
        for (int mt = 0; mt < 2; mt++) {
            #pragma unroll
            for (int nt = 0; nt < 8; nt++) {
                const int row = bm + wm + mt * 16 + grp;
                const int col = bn + wn + nt * 8 + kin * 2;
                float c0 = acc[mt][nt][0] * alpha;
                float c1 = acc[mt][nt][1] * alpha;
                float c2 = acc[mt][nt][2] * alpha;
                float c3 = acc[mt][nt][3] * alpha;
                if (mode == 0) {
                    const float bz0 = bias[col], bz1 = bias[col + 1];
                    c0 += bz0; c1 += bz1; c2 += bz0; c3 += bz1;
                    const int seg = col >> 10;          // uniform per tile
                    const int cc  = col & 1023;
                    if (seg == 0) {
                        *(__half2*)(P0 + (size_t)row * NC + cc)       = __floats2half2_rn(c0, c1);
                        *(__half2*)(P0 + (size_t)(row + 8) * NC + cc) = __floats2half2_rn(c2, c3);
                    } else if (seg == 1) {
                        *(__half2*)(P1 + (size_t)row * NC + cc)       = __floats2half2_rn(c0, c1);
                        *(__half2*)(P1 + (size_t)(row + 8) * NC + cc) = __floats2half2_rn(c2, c3);
                    } else {
                        P2[(size_t)(cc    ) * MTOT + row    ] = __float2half_rn(c0);
                        P2[(size_t)(cc + 1) * MTOT + row    ] = __float2half_rn(c1);
                        P2[(size_t)(cc    ) * MTOT + row + 8] = __float2half_rn(c2);
                        P2[(size_t)(cc + 1) * MTOT + row + 8] = __float2half_rn(c3);
                    }
                } else if (mode == 1) {
                    // exp + causal mask, unnormalized P' in fp16
                    __half* Pb = P0 + (size_t)z * sC;
                    float e0 = (col     <= row) ? __expf(c0) : 0.f;
                    float e1 = (col + 1 <= row) ? __expf(c1) : 0.f;
                    float e2 = (col     <= row + 8) ? __expf(c2) : 0.f;
                    float e3 = (col + 1 <= row + 8) ? __expf(c3) : 0.f;
                    *(__half2*)(Pb + (size_t)row * ldc + col)       = __floats2half2_rn(e0, e1);
                    *(__half2*)(Pb + (size_t)(row + 8) * ldc + col) = __floats2half2_rn(e2, e3);
                } else {
                    // softmax normalization folded into PV epilogue
                    const float s0 = rowinv[z * NTOK + row];
                    const float s1 = rowinv[z * NTOK + row + 8];
                    *(float2*)(Cb + (size_t)row * ldc + col) =
                        make_float2(c0 * s0, c1 * s0);
                    *(float2*)(Cb + (size_t)(row + 8) * ldc + col) =
                        make_float2(c2 * s1, c3 * s1);
                }
            }
        }
    }
}

// ---------------------------------------------------------------------------
// Elementwise fp32 -> fp16 copy
// ---------------------------------------------------------------------------
__global__ void half_copy(const float4* __restrict__ in, __half2* __restrict__ out,
                          int n4)
{
    const int i = blockIdx.x * blockDim.x + threadIdx.x;
    if (i < n4) {
        float4 v = in[i];
        out[i * 2    ] = __floats2half2_rn(v.x, v.y);
        out[i * 2 + 1] = __floats2half2_rn(v.z, v.w);
    }
}

// Concatenate bk|bq|bv into one 3072-wide fp32 bias
__global__ void concat_bias(const float* __restrict__ a, const float* __restrict__ b,
                            const float* __restrict__ c, float* __restrict__ o)
{
    const int i = blockIdx.x * blockDim.x + threadIdx.x;
    if (i < NC) {
        o[i]          = a[i];
        o[NC + i]     = b[i];
        o[2 * NC + i] = c[i];
    }
}

// ---------------------------------------------------------------------------
// Row sums of P' (fp16, causal-masked): inv[row] = 1 / sum.
// One warp per row; 8 warps (256 threads) per block; 1024 blocks.
// Row length rounded up to 128 (padding is exact zeros).
// ---------------------------------------------------------------------------
__global__ void row_sums(const __half* __restrict__ P, float* __restrict__ inv)
{
    const int row = blockIdx.x * 8 + (threadIdx.x >> 5);   // 0..8191
    const int lane = threadIdx.x & 31;
    const int z = row >> 11;
    const int t = row & (NTOK - 1);
    const int len = (t + 128) & ~127;                       // halfs, multiple of 128
    const float4* pr = (const float4*)(P + (size_t)z * NTOK * NTOK +
                                       (size_t)t * NTOK);   // 8 halfs per float4
    const int n8 = len >> 3;

    float s = 0.f;
    for (int i = lane; i < n8; i += 32) {
        const float4 v = pr[i];
        const __half2* h = (const __half2*)&v;
        float2 f0 = __half22float2(h[0]);
        float2 f1 = __half22float2(h[1]);
        float2 f2 = __half22float2(h[2]);
        float2 f3 = __half22float2(h[3]);
        s += (f0.x + f0.y) + (f1.x + f1.y) + (f2.x + f2.y) + (f3.x + f3.y);
    }
    #pragma unroll
    for (int o = 16; o > 0; o >>= 1) s += __shfl_xor_sync(0xffffffffu, s, o);
    if (lane == 0) inv[row] = 1.0f / s;
}

// ---------------------------------------------------------------------------
// Launch
// ---------------------------------------------------------------------------
extern "C" void kernel_launch(void* const* d_in, const int* in_sizes, int n_in,
                              void* d_out, int out_size)
{
    const float* x  = (const float*)d_in[0];
    const float* Wk = (const float*)d_in[1];
    const float* bk = (const float*)d_in[2];
    const float* Wq = (const float*)d_in[3];
    const float* bq = (const float*)d_in[4];
    const float* Wv = (const float*)d_in[5];
    const float* bv = (const float*)d_in[6];
    float* y = (float*)d_out;

    __half *xr, *wr, *q, *k, *vt, *pp;
    float *bb, *ginv;
    cudaGetSymbolAddress((void**)&xr, g_x);
    cudaGetSymbolAddress((void**)&wr, g_w);
    cudaGetSymbolAddress((void**)&bb, g_b);
    cudaGetSymbolAddress((void**)&q,  g_q);
    cudaGetSymbolAddress((void**)&k,  g_k);
    cudaGetSymbolAddress((void**)&vt, g_vt);
    cudaGetSymbolAddress((void**)&pp, g_p);
    cudaGetSymbolAddress((void**)&ginv, g_inv);

    cudaFuncSetAttribute(tc_gemm, cudaFuncAttributeMaxDynamicSharedMemorySize,
                         SMEM_BYTES);

    // 0) fp16-convert operands; concat biases
    const int n4x = MTOT * NC / 4;
    const int n4w = NC * NC / 4;
    half_copy<<<(n4x + 255) / 256, 256>>>((const float4*)x, (__half2*)xr, n4x);
    half_copy<<<(n4w + 255) / 256, 256>>>((const float4*)Wk, (__half2*)(wr                      ), n4w);
    half_copy<<<(n4w + 255) / 256, 256>>>((const float4*)Wq, (__half2*)(wr + (size_t)NC * NC    ), n4w);
    half_copy<<<(n4w + 255) / 256, 256>>>((const float4*)Wv, (__half2*)(wr + (size_t)2 * NC * NC), n4w);
    concat_bias<<<(NC + 255) / 256, 256>>>(bk, bq, bv, bb);

    // 1) Fused QKV projection (persistent): 1536 tiles
    tc_gemm<<<NSM_CTAS, 256, SMEM_BYTES>>>(xr, wr, bb, nullptr, k, q, vt, nullptr,
                                           NC, NC, NC, 0, 0, 0, 0,
                                           1.0f, 0, 1536);

    // 2) Scores (persistent): 544 lower-tri tiles -> P' = exp(alpha*S), fp16
    tc_gemm<<<NSM_CTAS, 256, SMEM_BYTES>>>(q, k, nullptr, nullptr, pp, nullptr,
                                           nullptr, nullptr,
                                           NC, NC, NC, NTOK,
                                           (long)NTOK * NC, (long)NTOK * NC,
                                           (long)NTOK * NTOK,
                                           0.03125f, 1, 544);

    // 3) Row sums of P' -> inv
    row_sums<<<MTOT / 8, 256>>>(pp, ginv);

    // 4) Y = diag(inv) * (P' @ V) (persistent): 512 tiles, balanced ranks
    tc_gemm<<<NSM_CTAS, 256, SMEM_BYTES>>>(pp, vt, nullptr, y, nullptr, nullptr,
                                           nullptr, ginv,
                                           NTOK, NTOK, MTOT, NC,
                                           (long)NTOK * NTOK, (long)NTOK,
                                           (long)NTOK * NC,
                                           1.0f, 2, 512);
}

// round 17
// speedup vs baseline: 1.0422x; 1.0172x over previous
#include <cuda_runtime.h>
#include <cuda_fp16.h>
#include <cstdint>

// ---------------------------------------------------------------------------
// Problem constants
// ---------------------------------------------------------------------------
#define NB   4
#define NTOK 2048
#define NC   1024
#define MTOT (NB * NTOK)   // 8192

// Scratch (__device__ globals: allocation-free rule)
__device__ __half g_x [(size_t)MTOT * NC];          // fp16 x
__device__ __half g_w [(size_t)3 * NC * NC];        // fp16 Wk|Wq|Wv
__device__ float  g_b [3 * NC];                     // concat bk|bq|bv (fp32)
__device__ __half g_q [(size_t)MTOT * NC];
__device__ __half g_k [(size_t)MTOT * NC];
__device__ __half g_vt[(size_t)NC * MTOT];          // V transposed: [C][B*T]
__device__ __half g_p [(size_t)NB * NTOK * NTOK];   // P' = exp(S) (fp16, masked)
__device__ float  g_inv[MTOT];                      // 1 / row sums of P'

__device__ __forceinline__ void mma_f16(float c[4], const uint32_t a[4],
                                        uint32_t b0, uint32_t b1) {
    asm volatile(
        "mma.sync.aligned.m16n8k16.row.col.f32.f16.f16.f32 "
        "{%0,%1,%2,%3}, {%4,%5,%6,%7}, {%8,%9}, {%0,%1,%2,%3};"
        : "+f"(c[0]), "+f"(c[1]), "+f"(c[2]), "+f"(c[3])
        : "r"(a[0]), "r"(a[1]), "r"(a[2]), "r"(a[3]), "r"(b0), "r"(b1));
}

__device__ __forceinline__ void ldsm_x4(uint32_t& r0, uint32_t& r1,
                                        uint32_t& r2, uint32_t& r3,
                                        uint32_t addr) {
    asm volatile("ldmatrix.sync.aligned.m8n8.x4.shared.b16 {%0,%1,%2,%3}, [%4];"
                 : "=r"(r0), "=r"(r1), "=r"(r2), "=r"(r3) : "r"(addr));
}

__device__ __forceinline__ uint32_t smem_u32(const void* p) {
    uint32_t a;
    asm("{ .reg .u64 t; cvta.to.shared.u64 t, %1; cvt.u32.u64 %0, t; }"
        : "=r"(a) : "l"(p));
    return a;
}

__device__ __forceinline__ void cp16(uint32_t dst, const void* src) {
    asm volatile("cp.async.cg.shared.global [%0], [%1], 16;"
                 :: "r"(dst), "l"(src));
}
#define CP_COMMIT()   asm volatile("cp.async.commit_group;" ::: "memory")
#define CP_WAIT1()    asm volatile("cp.async.wait_group 1;" ::: "memory")
#define CP_WAITALL()  asm volatile("cp.async.wait_all;" ::: "memory")

// ---------------------------------------------------------------------------
// fp16 mma.sync NT GEMM, cp.async 3-stage pipeline, BK=64 halfs.
// Block tile 128x128, 128 threads (4 warps, 2m x 2n), warp tile 64x64.
// ONE TILE PER CTA (dynamic HW balancing); 2 CTAs resident per SM.
// mode 0: QKV  — route cols to P0|P1|P2^T (fp16), +bias.
// mode 1: scores — lower-tri tiles (triangular bid mapping); epilogue writes
//                  exp(alpha*S) fp16 to P0 with causal mask col<=row.
// mode 2: PV  — K truncated at bm+128, heavy tiles scheduled first; epilogue
//               scales rows by rowinv[] (softmax normalization), C fp32.
// ---------------------------------------------------------------------------
#define STAGES 3
#define BMT 128
#define BNT 128
#define BK  64
#define ASTR_H 72                        // halfs per smem row (144 B)
#define ABUF_H (BMT * ASTR_H)            // 9216 halfs
#define STG_B  (2 * ABUF_H * 2)          // bytes per stage (A+B) = 36864
#define SMEM_BYTES (STAGES * STG_B)      // 110592

__device__ __forceinline__ void issue_loads(uint32_t sbase,
                                            const __half* Ab, const __half* Bb,
                                            long lda, long ldb, long koff, int tid)
{
    #pragma unroll
    for (int i = 0; i < 8; i++) {
        const int idx = i * 128 + tid;          // 0..1023
        const int row = idx >> 3;               // 0..127
        const int kq  = (idx & 7) * 8;          // halfs: 0..56
        cp16(sbase + (uint32_t)(row * ASTR_H + kq) * 2,
             Ab + (size_t)row * lda + koff + kq);
    }
    #pragma unroll
    for (int i = 0; i < 8; i++) {
        const int idx = i * 128 + tid;
        const int row = idx >> 3;
        const int kq  = (idx & 7) * 8;
        cp16(sbase + (uint32_t)(ABUF_H + row * ASTR_H + kq) * 2,
             Bb + (size_t)row * ldb + koff + kq);
    }
}

__global__ void __launch_bounds__(128, 2)
tc_gemm(const __half* __restrict__ A, const __half* __restrict__ B,
        const float* __restrict__ bias, float* __restrict__ C,
        __half* __restrict__ P0, __half* __restrict__ P1, __half* __restrict__ P2,
        const float* __restrict__ rowinv,
        int K, long lda, long ldb, long ldc,
        long sA, long sB, long sC,
        float alpha, int mode)
{
    extern __shared__ __half sm[];

    const int tid  = threadIdx.x;
    const int wid  = tid >> 5;
    const int lane = tid & 31;
    const int wm   = (wid & 1) * 64;
    const int wn   = (wid >> 1) * 64;
    const int grp  = lane >> 2;
    const int kin  = lane & 3;

    const int mat = lane >> 3;          // 0..3
    const int r8  = lane & 7;
    const uint32_t smb = smem_u32(sm);
    const uint32_t aaddr0 = smb +
        (uint32_t)(wm + (mat & 1) * 8 + r8) * (ASTR_H * 2) + (mat >> 1) * 16;
    const uint32_t baddr0 = smb + ABUF_H * 2 +
        (uint32_t)(wn + (mat & 1) * 8 + r8) * (ASTR_H * 2) + (mat >> 1) * 16;

    // ---- tile mapping (one tile per CTA) ----
    const int t = blockIdx.x;
    int bm, bn, z, nch;
    if (mode == 0) {                     // QKV: 24 n-tiles x 64 m-tiles
        bm = (t / 24) * BMT;
        bn = (t % 24) * BNT;
        z  = 0;
        nch = K / BK;
    } else if (mode == 1) {              // scores: lower-tri tiles, 136/batch
        z = t / 136;
        const int tri = t - z * 136;
        int i = (int)((sqrtf(8.0f * tri + 1.0f) - 1.0f) * 0.5f);
        while ((i + 1) * (i + 2) / 2 <= tri) i++;
        while (i * (i + 1) / 2 > tri) i--;
        const int j = tri - i * (i + 1) / 2;
        bm = i * BMT;
        bn = j * BNT;
        nch = K / BK;
    } else {                             // PV: heavy (large bm) tiles first
        const int level = t >> 5;        // 0..15 (heavy -> light)
        const int idx   = t & 31;
        bm = (15 - level) * BMT;
        z  = idx >> 3;
        bn = (idx & 7) * BNT;
        nch = (bm + BMT) / BK;
    }

    const __half* Ab = A + (size_t)z * sA + (size_t)bm * lda;
    const __half* Bb = B + (size_t)z * sB + (size_t)bn * ldb;
    float*        Cb = C ? (C + (size_t)z * sC) : nullptr;

    float acc[4][8][4] = {};

    // ---- prologue: prefetch STAGES-1 chunks ----
    #pragma unroll
    for (int s = 0; s < STAGES - 1; s++) {
        if (s < nch)
            issue_loads(smb + (uint32_t)s * STG_B, Ab, Bb, lda, ldb,
                        (long)s * BK, tid);
        CP_COMMIT();
    }

    for (int kc = 0; kc < nch; kc++) {
        CP_WAIT1();
        __syncthreads();

        const int nk = kc + STAGES - 1;
        if (nk < nch)
            issue_loads(smb + (uint32_t)(nk % STAGES) * STG_B,
                        Ab, Bb, lda, ldb, (long)nk * BK, tid);
        CP_COMMIT();

        const uint32_t soff = (uint32_t)(kc % STAGES) * STG_B;
        const uint32_t abase = aaddr0 + soff;
        const uint32_t bbase = baddr0 + soff;

        #pragma unroll
        for (int ks = 0; ks < 4; ks++) {       // 4 x k16 = 64
            uint32_t a[4][4];
            #pragma unroll
            for (int mt = 0; mt < 4; mt++)
                ldsm_x4(a[mt][0], a[mt][1], a[mt][2], a[mt][3],
                        abase + mt * (16 * ASTR_H * 2) + ks * 32);
            #pragma unroll
            for (int np = 0; np < 4; np++) {   // n16 groups
                uint32_t b0, b1, b2, b3;
                ldsm_x4(b0, b1, b2, b3,
                        bbase + np * (16 * ASTR_H * 2) + ks * 32);
                #pragma unroll
                for (int mt = 0; mt < 4; mt++) {
                    mma_f16(acc[mt][np * 2    ], a[mt], b0, b2);
                    mma_f16(acc[mt][np * 2 + 1], a[mt], b1, b3);
                }
            }
        }
    }
    CP_WAITALL();

    // ---- epilogue ----
    #pragma unroll
    for (int mt = 0; mt < 4; mt++) {
        #pragma unroll
        for (int nt = 0; nt < 8; nt++) {
            const int row = bm + wm + mt * 16 + grp;
            const int col = bn + wn + nt * 8 + kin * 2;
            float c0 = acc[mt][nt][0] * alpha;
            float c1 = acc[mt][nt][1] * alpha;
            float c2 = acc[mt][nt][2] * alpha;
            float c3 = acc[mt][nt][3] * alpha;
            if (mode == 0) {
                const float bz0 = bias[col], bz1 = bias[col + 1];
                c0 += bz0; c1 += bz1; c2 += bz0; c3 += bz1;
                const int seg = col >> 10;          // uniform per tile
                const int cc  = col & 1023;
                if (seg == 0) {
                    *(__half2*)(P0 + (size_t)row * NC + cc)       = __floats2half2_rn(c0, c1);
                    *(__half2*)(P0 + (size_t)(row + 8) * NC + cc) = __floats2half2_rn(c2, c3);
                } else if (seg == 1) {
                    *(__half2*)(P1 + (size_t)row * NC + cc)       = __floats2half2_rn(c0, c1);
                    *(__half2*)(P1 + (size_t)(row + 8) * NC + cc) = __floats2half2_rn(c2, c3);
                } else {
                    P2[(size_t)(cc    ) * MTOT + row    ] = __float2half_rn(c0);
                    P2[(size_t)(cc + 1) * MTOT + row    ] = __float2half_rn(c1);
                    P2[(size_t)(cc    ) * MTOT + row + 8] = __float2half_rn(c2);
                    P2[(size_t)(cc + 1) * MTOT + row + 8] = __float2half_rn(c3);
                }
            } else if (mode == 1) {
                // exp + causal mask, unnormalized P' in fp16
                __half* Pb = P0 + (size_t)z * sC;
                float e0 = (col     <= row) ? __expf(c0) : 0.f;
                float e1 = (col + 1 <= row) ? __expf(c1) : 0.f;
                float e2 = (col     <= row + 8) ? __expf(c2) : 0.f;
                float e3 = (col + 1 <= row + 8) ? __expf(c3) : 0.f;
                *(__half2*)(Pb + (size_t)row * ldc + col)       = __floats2half2_rn(e0, e1);
                *(__half2*)(Pb + (size_t)(row + 8) * ldc + col) = __floats2half2_rn(e2, e3);
            } else {
                // softmax normalization folded into PV epilogue
                const float s0 = rowinv[z * NTOK + row];
                const float s1 = rowinv[z * NTOK + row + 8];
                *(float2*)(Cb + (size_t)row * ldc + col) =
                    make_float2(c0 * s0, c1 * s0);
                *(float2*)(Cb + (size_t)(row + 8) * ldc + col) =
                    make_float2(c2 * s1, c3 * s1);
            }
        }
    }
}

// ---------------------------------------------------------------------------
// Merged prep: fp16-convert x + Wk|Wq|Wv, concat biases (single launch)
// ---------------------------------------------------------------------------
__global__ void prep_all(const float4* __restrict__ x,
                         const float4* __restrict__ wk,
                         const float4* __restrict__ wq,
                         const float4* __restrict__ wv,
                         const float*  __restrict__ bk,
                         const float*  __restrict__ bq,
                         const float*  __restrict__ bv,
                         __half2* __restrict__ xr, __half2* __restrict__ wr,
                         float* __restrict__ bb,
                         int n4x, int n4w)
{
    const int i = blockIdx.x * blockDim.x + threadIdx.x;
    const int n4t = n4x + 3 * n4w;
    if (i < n4t) {
        const float4* src;
        __half2* dst;
        int j;
        if (i < n4x)                { src = x;  dst = xr;                       j = i; }
        else if (i < n4x + n4w)     { src = wk; dst = wr;                       j = i - n4x; }
        else if (i < n4x + 2 * n4w) { src = wq; dst = wr + (size_t)n4w * 2;     j = i - n4x - n4w; }
        else                        { src = wv; dst = wr + (size_t)n4w * 4;     j = i - n4x - 2 * n4w; }
        const float4 v = src[j];
        dst[j * 2    ] = __floats2half2_rn(v.x, v.y);
        dst[j * 2 + 1] = __floats2half2_rn(v.z, v.w);
    } else {
        const int b = i - n4t;
        if (b < NC) {
            bb[b]          = bk[b];
            bb[NC + b]     = bq[b];
            bb[2 * NC + b] = bv[b];
        }
    }
}

// ---------------------------------------------------------------------------
// Row sums of P' (fp16, causal-masked): inv[row] = 1 / sum.
// One warp per row; 8 warps (256 threads) per block; 1024 blocks.
// Row length rounded up to 128 (padding is exact zeros).
// ---------------------------------------------------------------------------
__global__ void row_sums(const __half* __restrict__ P, float* __restrict__ inv)
{
    const int row = blockIdx.x * 8 + (threadIdx.x >> 5);   // 0..8191
    const int lane = threadIdx.x & 31;
    const int z = row >> 11;
    const int t = row & (NTOK - 1);
    const int len = (t + 128) & ~127;                       // halfs, multiple of 128
    const float4* pr = (const float4*)(P + (size_t)z * NTOK * NTOK +
                                       (size_t)t * NTOK);   // 8 halfs per float4
    const int n8 = len >> 3;

    float s = 0.f;
    for (int i = lane; i < n8; i += 32) {
        const float4 v = pr[i];
        const __half2* h = (const __half2*)&v;
        float2 f0 = __half22float2(h[0]);
        float2 f1 = __half22float2(h[1]);
        float2 f2 = __half22float2(h[2]);
        float2 f3 = __half22float2(h[3]);
        s += (f0.x + f0.y) + (f1.x + f1.y) + (f2.x + f2.y) + (f3.x + f3.y);
    }
    #pragma unroll
    for (int o = 16; o > 0; o >>= 1) s += __shfl_xor_sync(0xffffffffu, s, o);
    if (lane == 0) inv[row] = 1.0f / s;
}

// ---------------------------------------------------------------------------
// Launch
// ---------------------------------------------------------------------------
extern "C" void kernel_launch(void* const* d_in, const int* in_sizes, int n_in,
                              void* d_out, int out_size)
{
    const float* x  = (const float*)d_in[0];
    const float* Wk = (const float*)d_in[1];
    const float* bk = (const float*)d_in[2];
    const float* Wq = (const float*)d_in[3];
    const float* bq = (const float*)d_in[4];
    const float* Wv = (const float*)d_in[5];
    const float* bv = (const float*)d_in[6];
    float* y = (float*)d_out;

    __half *xr, *wr, *q, *k, *vt, *pp;
    float *bb, *ginv;
    cudaGetSymbolAddress((void**)&xr, g_x);
    cudaGetSymbolAddress((void**)&wr, g_w);
    cudaGetSymbolAddress((void**)&bb, g_b);
    cudaGetSymbolAddress((void**)&q,  g_q);
    cudaGetSymbolAddress((void**)&k,  g_k);
    cudaGetSymbolAddress((void**)&vt, g_vt);
    cudaGetSymbolAddress((void**)&pp, g_p);
    cudaGetSymbolAddress((void**)&ginv, g_inv);

    cudaFuncSetAttribute(tc_gemm, cudaFuncAttributeMaxDynamicSharedMemorySize,
                         SMEM_BYTES);

    // 0) single prep launch: fp16 conversions + bias concat
    const int n4x = MTOT * NC / 4;
    const int n4w = NC * NC / 4;
    const int ntot = n4x + 3 * n4w + NC;
    prep_all<<<(ntot + 255) / 256, 256>>>((const float4*)x, (const float4*)Wk,
                                          (const float4*)Wq, (const float4*)Wv,
                                          bk, bq, bv,
                                          (__half2*)xr, (__half2*)wr, bb,
                                          n4x, n4w);

    // 1) Fused QKV projection: 1536 tiles, dynamic HW balancing
    tc_gemm<<<1536, 128, SMEM_BYTES>>>(xr, wr, bb, nullptr, k, q, vt, nullptr,
                                       NC, NC, NC, 0, 0, 0, 0,
                                       1.0f, 0);

    // 2) Scores: 544 lower-tri tiles -> P' = exp(alpha*S), fp16
    tc_gemm<<<544, 128, SMEM_BYTES>>>(q, k, nullptr, nullptr, pp, nullptr,
                                      nullptr, nullptr,
                                      NC, NC, NC, NTOK,
                                      (long)NTOK * NC, (long)NTOK * NC,
                                      (long)NTOK * NTOK,
                                      0.03125f, 1);

    // 3) Row sums of P' -> inv
    row_sums<<<MTOT / 8, 256>>>(pp, ginv);

    // 4) Y = diag(inv) * (P' @ V): 512 tiles, heavy-first scheduling
    tc_gemm<<<512, 128, SMEM_BYTES>>>(pp, vt, nullptr, y, nullptr, nullptr,
                                      nullptr, ginv,
                                      NTOK, NTOK, MTOT, NC,
                                      (long)NTOK * NTOK, (long)NTOK,
                                      (long)NTOK * NC,
                                      1.0f, 2);
}